// round 1
// baseline (speedup 1.0000x reference)
#include <cuda_runtime.h>
#include <cuda_bf16.h>
#include <math.h>

// Problem dims
#define NQ 8192
#define NK 8192
#define DIM 512
#define SHIFT 55.0f
#define CSCALE 0.01f

// Scratch (no cudaMalloc allowed)
__device__ float g_qq[NQ];
__device__ float g_kk[NK];
__device__ float g_rinv[NQ];   // reciprocal of row sums

// ---------------------------------------------------------------------------
// Kernel 1: sum of squares for Q rows and K rows. One warp per row.
// grid: 2*8192 warps = 2048 blocks x 256 threads
// ---------------------------------------------------------------------------
__global__ void sumsq_kernel(const float* __restrict__ Q, const float* __restrict__ Kp) {
    int gw   = (blockIdx.x * blockDim.x + threadIdx.x) >> 5;
    int lane = threadIdx.x & 31;
    const float* x;
    float* o;
    int row;
    if (gw < NQ) { x = Q;  o = g_qq; row = gw; }
    else         { x = Kp; o = g_kk; row = gw - NQ; }
    const float4* p = reinterpret_cast<const float4*>(x + (size_t)row * DIM);
    float s = 0.0f;
#pragma unroll
    for (int c = 0; c < DIM / 128; c++) {
        float4 v = p[c * 32 + lane];
        s = fmaf(v.x, v.x, s);
        s = fmaf(v.y, v.y, s);
        s = fmaf(v.z, v.z, s);
        s = fmaf(v.w, v.w, s);
    }
#pragma unroll
    for (int off = 16; off; off >>= 1) s += __shfl_xor_sync(0xFFFFFFFFu, s, off);
    if (lane == 0) o[row] = s;
}

// ---------------------------------------------------------------------------
// Score epilogue: exp(score + SHIFT). Scores are always <= ~-40 here, so a
// fixed shift replaces row-max subtraction (mathematically identical softmax).
// ---------------------------------------------------------------------------
__device__ __forceinline__ float score_exp(float qk, float qq, float kk) {
    float norm2 = fmaxf(qq + kk - 2.0f * qk, 0.0f);
    float qdot  = qq - qk;
    float kdot  = qk - kk;
    float qd = sqrtf(fmaf(CSCALE * qdot, qdot, norm2));
    float kd = sqrtf(fmaf(CSCALE * kdot, kdot, norm2));
    return __expf(fmaf(-0.5f, qd + kd, SHIFT));
}

// ---------------------------------------------------------------------------
// Kernel 2: 128x128x8 fp32 tiled GEMM (QK^T), fused score+exp epilogue.
// 256 threads = 16x16, each computes 8x8 (two 4-wide groups per dim).
// ---------------------------------------------------------------------------
__global__ void __launch_bounds__(256)
gemm_score_kernel(const float* __restrict__ Q, const float* __restrict__ Kp,
                  float* __restrict__ out) {
    __shared__ float As[8][132];   // [k][m], padded
    __shared__ float Bs[8][132];   // [k][n], padded

    const int tid = threadIdx.x;
    const int bm = blockIdx.y;
    const int bn = blockIdx.x;
    const int tx = tid & 15;
    const int ty = tid >> 4;

    // loader mapping: each thread loads one float4 from Q tile and one from K tile
    const int lrow = tid >> 1;          // 0..127
    const int lcol = (tid & 1) << 2;    // 0 or 4

    const float* qptr = Q  + (size_t)(bm * 128 + lrow) * DIM + lcol;
    const float* kptr = Kp + (size_t)(bn * 128 + lrow) * DIM + lcol;

    float acc[8][8];
#pragma unroll
    for (int i = 0; i < 8; i++)
#pragma unroll
        for (int j = 0; j < 8; j++) acc[i][j] = 0.0f;

    for (int k0 = 0; k0 < DIM; k0 += 8) {
        float4 qa = *reinterpret_cast<const float4*>(qptr + k0);
        float4 kb = *reinterpret_cast<const float4*>(kptr + k0);
        __syncthreads();
        As[lcol + 0][lrow] = qa.x;
        As[lcol + 1][lrow] = qa.y;
        As[lcol + 2][lrow] = qa.z;
        As[lcol + 3][lrow] = qa.w;
        Bs[lcol + 0][lrow] = kb.x;
        Bs[lcol + 1][lrow] = kb.y;
        Bs[lcol + 2][lrow] = kb.z;
        Bs[lcol + 3][lrow] = kb.w;
        __syncthreads();
#pragma unroll
        for (int kk = 0; kk < 8; kk++) {
            float a[8], b[8];
#pragma unroll
            for (int i = 0; i < 4; i++) {
                a[i]     = As[kk][ty * 4 + i];
                a[4 + i] = As[kk][64 + ty * 4 + i];
                b[i]     = Bs[kk][tx * 4 + i];
                b[4 + i] = Bs[kk][64 + tx * 4 + i];
            }
#pragma unroll
            for (int i = 0; i < 8; i++)
#pragma unroll
                for (int j = 0; j < 8; j++) acc[i][j] = fmaf(a[i], b[j], acc[i][j]);
        }
    }

    // epilogue: fragment (i,j) -> row (i>>2)*64 + ty*4 + (i&3), col (j>>2)*64 + tx*4 + (j&3)
    float qqv[8], kkv[8];
#pragma unroll
    for (int i = 0; i < 8; i++) {
        int r = ((i >> 2) * 64) + ty * 4 + (i & 3);
        qqv[i] = g_qq[bm * 128 + r];
        int c = ((i >> 2) * 64) + tx * 4 + (i & 3);
        kkv[i] = g_kk[bn * 128 + c];
    }

#pragma unroll
    for (int i = 0; i < 8; i++) {
        int r = ((i >> 2) * 64) + ty * 4 + (i & 3);
        size_t base = (size_t)(bm * 128 + r) * NK + (size_t)bn * 128;
#pragma unroll
        for (int g = 0; g < 2; g++) {
            float4 v;
            v.x = score_exp(acc[i][g * 4 + 0], qqv[i], kkv[g * 4 + 0]);
            v.y = score_exp(acc[i][g * 4 + 1], qqv[i], kkv[g * 4 + 1]);
            v.z = score_exp(acc[i][g * 4 + 2], qqv[i], kkv[g * 4 + 2]);
            v.w = score_exp(acc[i][g * 4 + 3], qqv[i], kkv[g * 4 + 3]);
            *reinterpret_cast<float4*>(out + base + g * 64 + tx * 4) = v;
        }
    }
}

// ---------------------------------------------------------------------------
// Kernel 3: per-row sum of exp values -> store reciprocal. One block per row.
// ---------------------------------------------------------------------------
__global__ void rowsum_kernel(const float* __restrict__ out) {
    int row = blockIdx.x;
    const float4* p = reinterpret_cast<const float4*>(out + (size_t)row * NK);
    float s = 0.0f;
    for (int i = threadIdx.x; i < NK / 4; i += blockDim.x) {
        float4 v = p[i];
        s += (v.x + v.y) + (v.z + v.w);
    }
#pragma unroll
    for (int off = 16; off; off >>= 1) s += __shfl_xor_sync(0xFFFFFFFFu, s, off);
    __shared__ float red[8];
    if ((threadIdx.x & 31) == 0) red[threadIdx.x >> 5] = s;
    __syncthreads();
    if (threadIdx.x < 8) {
        float v = red[threadIdx.x];
#pragma unroll
        for (int off = 4; off; off >>= 1) v += __shfl_xor_sync(0xFFu, v, off);
        if (threadIdx.x == 0) g_rinv[row] = 1.0f / v;
    }
}

// ---------------------------------------------------------------------------
// Kernel 4: normalize in place. One block per row.
// ---------------------------------------------------------------------------
__global__ void normalize_kernel(float* __restrict__ out) {
    int row = blockIdx.x;
    float inv = g_rinv[row];
    float4* p = reinterpret_cast<float4*>(out + (size_t)row * NK);
    for (int i = threadIdx.x; i < NK / 4; i += blockDim.x) {
        float4 v = p[i];
        v.x *= inv; v.y *= inv; v.z *= inv; v.w *= inv;
        p[i] = v;
    }
}

// ---------------------------------------------------------------------------
extern "C" void kernel_launch(void* const* d_in, const int* in_sizes, int n_in,
                              void* d_out, int out_size) {
    const float* Q  = (const float*)d_in[0];
    const float* Kp = (const float*)d_in[1];
    float* out = (float*)d_out;

    // 1. row sums-of-squares (2*8192 warps)
    sumsq_kernel<<<(2 * NQ) / 8, 256>>>(Q, Kp);

    // 2. fused GEMM + score + exp
    dim3 grid(NK / 128, NQ / 128);
    gemm_score_kernel<<<grid, 256>>>(Q, Kp, out);

    // 3. row sums -> reciprocals
    rowsum_kernel<<<NQ, 256>>>(out);

    // 4. normalize
    normalize_kernel<<<NQ, 256>>>(out);
}

// round 4
// speedup vs baseline: 1.9936x; 1.9936x over previous
#include <cuda_runtime.h>
#include <cuda_bf16.h>
#include <cstdint>
#include <math.h>

#define NQ 8192
#define NK 8192
#define DIM 512
#define CSCALE 0.01f
// exp(-0.5*(qd+kd)+55) = 2^(-0.5*log2e*(qd+kd) + 55*log2e)
#define NEG_HALF_LOG2E (-0.72134752044448170f)
#define SHIFT_LOG2E    (79.34822724889299f)

// ---------------------------------------------------------------------------
// Scratch (static device arrays; no runtime allocation)
// ---------------------------------------------------------------------------
__device__ __nv_bfloat16 g_qh[NQ * DIM];
__device__ __nv_bfloat16 g_ql[NQ * DIM];
__device__ __nv_bfloat16 g_kh[NK * DIM];
__device__ __nv_bfloat16 g_kl[NK * DIM];
__device__ float g_qq[NQ];
__device__ float g_kk[NK];
__device__ float g_rsum[NQ];

// ---------------------------------------------------------------------------
// helpers
// ---------------------------------------------------------------------------
__device__ __forceinline__ uint32_t smem_u32(const void* p) {
    uint32_t a;
    asm("{ .reg .u64 t; cvta.to.shared.u64 t, %1; cvt.u32.u64 %0, t; }" : "=r"(a) : "l"(p));
    return a;
}

// SW64 swizzle for 64-byte rows: XOR bits[5:4] with bits[8:7]
#define SWZ64(off) ((off) ^ (((off) >> 3) & 0x30))

__device__ __forceinline__ void cp_async16(uint32_t dst, const void* src) {
    asm volatile("cp.async.cg.shared.global [%0], [%1], 16;" :: "r"(dst), "l"(src));
}

__device__ __forceinline__ void ldsm_x4(uint32_t& r0, uint32_t& r1, uint32_t& r2, uint32_t& r3,
                                        uint32_t addr) {
    asm volatile("ldmatrix.sync.aligned.m8n8.x4.shared.b16 {%0,%1,%2,%3}, [%4];"
                 : "=r"(r0), "=r"(r1), "=r"(r2), "=r"(r3) : "r"(addr));
}

__device__ __forceinline__ void mma16816(float* c, uint32_t a0, uint32_t a1, uint32_t a2,
                                         uint32_t a3, uint32_t b0, uint32_t b1) {
    asm volatile(
        "mma.sync.aligned.m16n8k16.row.col.f32.bf16.bf16.f32 "
        "{%0,%1,%2,%3}, {%4,%5,%6,%7}, {%8,%9}, {%0,%1,%2,%3};"
        : "+f"(c[0]), "+f"(c[1]), "+f"(c[2]), "+f"(c[3])
        : "r"(a0), "r"(a1), "r"(a2), "r"(a3), "r"(b0), "r"(b1));
}

__device__ __forceinline__ float fsqrt_approx(float x) {
    float r; asm("sqrt.approx.f32 %0, %1;" : "=f"(r) : "f"(x)); return r;
}
__device__ __forceinline__ float fexp2_approx(float x) {
    float r; asm("ex2.approx.f32 %0, %1;" : "=f"(r) : "f"(x)); return r;
}

// exp(score + 55) with fixed shift (softmax-invariant; scores always << 0)
__device__ __forceinline__ float score_exp(float qk, float qq, float kk) {
    float norm2 = fmaxf(qq + kk - 2.0f * qk, 0.0f);
    float qdot  = qq - qk;
    float kdot  = qk - kk;
    float qd = fsqrt_approx(fmaf(CSCALE * qdot, qdot, norm2));
    float kd = fsqrt_approx(fmaf(CSCALE * kdot, kdot, norm2));
    return fexp2_approx(fmaf(NEG_HALF_LOG2E, qd + kd, SHIFT_LOG2E));
}

// ---------------------------------------------------------------------------
// Kernel 1: per-row sumsq + bf16 hi/lo split. One warp per row. Zeroes g_rsum.
// ---------------------------------------------------------------------------
__global__ void __launch_bounds__(256)
prep_kernel(const float* __restrict__ Q, const float* __restrict__ Kp) {
    int gw   = (blockIdx.x * blockDim.x + threadIdx.x) >> 5;
    int lane = threadIdx.x & 31;
    bool isQ = gw < NQ;
    int row  = isQ ? gw : gw - NQ;
    const float4* src = reinterpret_cast<const float4*>((isQ ? Q : Kp) + (size_t)row * DIM);
    __nv_bfloat16* hi = isQ ? g_qh : g_kh;
    __nv_bfloat16* lo = isQ ? g_ql : g_kl;

    float s = 0.0f;
#pragma unroll
    for (int i = 0; i < DIM / 128; i++) {
        float4 v = src[i * 32 + lane];
        s = fmaf(v.x, v.x, s); s = fmaf(v.y, v.y, s);
        s = fmaf(v.z, v.z, s); s = fmaf(v.w, v.w, s);

        __nv_bfloat16 h0 = __float2bfloat16(v.x);
        __nv_bfloat16 h1 = __float2bfloat16(v.y);
        __nv_bfloat16 h2 = __float2bfloat16(v.z);
        __nv_bfloat16 h3 = __float2bfloat16(v.w);
        __nv_bfloat16 l0 = __float2bfloat16(v.x - __bfloat162float(h0));
        __nv_bfloat16 l1 = __float2bfloat16(v.y - __bfloat162float(h1));
        __nv_bfloat16 l2 = __float2bfloat16(v.z - __bfloat162float(h2));
        __nv_bfloat16 l3 = __float2bfloat16(v.w - __bfloat162float(h3));

        int col = (i * 32 + lane) * 4;
        __nv_bfloat162 h01 = __nv_bfloat162(h0, h1);
        __nv_bfloat162 h23 = __nv_bfloat162(h2, h3);
        __nv_bfloat162 l01 = __nv_bfloat162(l0, l1);
        __nv_bfloat162 l23 = __nv_bfloat162(l2, l3);
        uint2 hu = make_uint2(*reinterpret_cast<uint32_t*>(&h01), *reinterpret_cast<uint32_t*>(&h23));
        uint2 lu = make_uint2(*reinterpret_cast<uint32_t*>(&l01), *reinterpret_cast<uint32_t*>(&l23));
        *reinterpret_cast<uint2*>(hi + (size_t)row * DIM + col) = hu;
        *reinterpret_cast<uint2*>(lo + (size_t)row * DIM + col) = lu;
    }
#pragma unroll
    for (int off = 16; off; off >>= 1) s += __shfl_xor_sync(0xFFFFFFFFu, s, off);
    if (lane == 0) {
        if (isQ) { g_qq[row] = s; g_rsum[row] = 0.0f; }
        else     { g_kk[row] = s; }
    }
}

// ---------------------------------------------------------------------------
// Kernel 2: mma.sync bf16 split GEMM (K_eff=1536) + fused score/exp epilogue.
// CTA tile 128x128, 8 warps (2 x 4), warptile 64x32, K-chunk 32, double buffer.
// ---------------------------------------------------------------------------
#define NCHUNK 48
#define CK 32
#define BUFB 8192   // 128 rows x 64 bytes

__global__ void __launch_bounds__(256, 2)
gemm_score_kernel(float* __restrict__ out) {
    __shared__ __align__(128) uint8_t sA[2 * BUFB];
    __shared__ __align__(128) uint8_t sB[2 * BUFB];
    __shared__ float sqq[128];
    __shared__ float skk[128];

    const int tid  = threadIdx.x;
    const int wid  = tid >> 5;
    const int lane = tid & 31;
    const int bm = blockIdx.y;
    const int bn = blockIdx.x;
    const int warp_m = wid & 1;     // 0..1 -> 64-row half
    const int warp_n = wid >> 1;    // 0..3 -> 32-col quarter

    const uint32_t sa_base = smem_u32(sA);
    const uint32_t sb_base = smem_u32(sB);

    // per-thread qq/kk staging
    if (tid < 128) {
        sqq[tid] = g_qq[bm * 128 + tid];
        skk[tid] = g_kk[bn * 128 + tid];
    }

    // --- precompute per-lane ldmatrix byte offsets (within a buffer) ---
    uint32_t offA[4][2], offB[2][2];
#pragma unroll
    for (int mt = 0; mt < 4; mt++) {
        int m = warp_m * 64 + mt * 16 + (lane & 15);
#pragma unroll
        for (int ks = 0; ks < 2; ks++) {
            int o = m * 64 + ks * 32 + (lane >> 4) * 16;
            offA[mt][ks] = SWZ64(o);
        }
    }
#pragma unroll
    for (int nt2 = 0; nt2 < 2; nt2++) {
        int n = warp_n * 32 + nt2 * 16 + (lane & 7) + ((lane >> 4) & 1) * 8;
#pragma unroll
        for (int ks = 0; ks < 2; ks++) {
            int o = n * 64 + ks * 32 + ((lane >> 3) & 1) * 16;
            offB[nt2][ks] = SWZ64(o);
        }
    }

    // loader: per chunk each thread moves 4 x 16B for A and for B
    const int lrow = tid >> 1;            // 0..127 (2 threads per 64B row)
    const int lseg = (tid & 1) * 2;       // segment pairs {0,1} or {2,3}

    auto issue_chunk = [&](int c, int buf) {
        const __nv_bfloat16 *as, *bs;
        if (c < 16)      { as = g_qh; bs = g_kh; }
        else if (c < 32) { as = g_qh; bs = g_kl; }
        else             { as = g_ql; bs = g_kh; }
        int kc = (c & 15) * CK;
        const __nv_bfloat16* ag = as + (size_t)(bm * 128 + lrow) * DIM + kc;
        const __nv_bfloat16* bg = bs + (size_t)(bn * 128 + lrow) * DIM + kc;
        uint32_t sa = sa_base + buf * BUFB;
        uint32_t sbb = sb_base + buf * BUFB;
#pragma unroll
        for (int i = 0; i < 2; i++) {
            int seg = lseg + i;                       // 16B segment 0..3
            uint32_t off = SWZ64(lrow * 64 + seg * 16);
            cp_async16(sa  + off, ag + seg * 8);
            cp_async16(sbb + off, bg + seg * 8);
        }
        asm volatile("cp.async.commit_group;" ::: "memory");
    };

    float acc[4][4][4];
#pragma unroll
    for (int mt = 0; mt < 4; mt++)
#pragma unroll
        for (int nt = 0; nt < 4; nt++)
#pragma unroll
            for (int i = 0; i < 4; i++) acc[mt][nt][i] = 0.0f;

    issue_chunk(0, 0);

    for (int c = 0; c < NCHUNK; c++) {
        if (c + 1 < NCHUNK) {
            issue_chunk(c + 1, (c + 1) & 1);
            asm volatile("cp.async.wait_group 1;" ::: "memory");
        } else {
            asm volatile("cp.async.wait_group 0;" ::: "memory");
        }
        __syncthreads();

        uint32_t sa = sa_base + (c & 1) * BUFB;
        uint32_t sbb = sb_base + (c & 1) * BUFB;
#pragma unroll
        for (int ks = 0; ks < 2; ks++) {
            uint32_t a[4][4];
#pragma unroll
            for (int mt = 0; mt < 4; mt++)
                ldsm_x4(a[mt][0], a[mt][1], a[mt][2], a[mt][3], sa + offA[mt][ks]);
            uint32_t b[2][4];
#pragma unroll
            for (int nt2 = 0; nt2 < 2; nt2++)
                ldsm_x4(b[nt2][0], b[nt2][1], b[nt2][2], b[nt2][3], sbb + offB[nt2][ks]);
#pragma unroll
            for (int mt = 0; mt < 4; mt++) {
#pragma unroll
                for (int nt = 0; nt < 4; nt++) {
                    const uint32_t* bb = b[nt >> 1];
                    int h = (nt & 1) * 2;
                    mma16816(acc[mt][nt], a[mt][0], a[mt][1], a[mt][2], a[mt][3],
                             bb[h], bb[h + 1]);
                }
            }
        }
        __syncthreads();
    }

    // --- epilogue: score/exp on fragments, row sums, sector-aligned stores ---
#pragma unroll
    for (int mt = 0; mt < 4; mt++) {
        int lrow0 = warp_m * 64 + mt * 16 + (lane >> 2);
        float qq0 = sqq[lrow0];
        float qq1 = sqq[lrow0 + 8];
        float s0 = 0.0f, s1 = 0.0f;
        size_t r0base = (size_t)(bm * 128 + lrow0) * NK + bn * 128;
#pragma unroll
        for (int nt = 0; nt < 4; nt++) {
            int lcol = warp_n * 32 + nt * 8 + (lane & 3) * 2;
            float kk0 = skk[lcol];
            float kk1 = skk[lcol + 1];
            float* aa = acc[mt][nt];
            float e00 = score_exp(aa[0], qq0, kk0);
            float e01 = score_exp(aa[1], qq0, kk1);
            float e10 = score_exp(aa[2], qq1, kk0);
            float e11 = score_exp(aa[3], qq1, kk1);
            s0 += e00 + e01;
            s1 += e10 + e11;
            *reinterpret_cast<float2*>(out + r0base + lcol)            = make_float2(e00, e01);
            *reinterpret_cast<float2*>(out + r0base + 8 * NK + lcol)   = make_float2(e10, e11);
        }
        // quad reduce (lanes sharing a row differ in bits 0..1)
        s0 += __shfl_xor_sync(0xFFFFFFFFu, s0, 1);
        s0 += __shfl_xor_sync(0xFFFFFFFFu, s0, 2);
        s1 += __shfl_xor_sync(0xFFFFFFFFu, s1, 1);
        s1 += __shfl_xor_sync(0xFFFFFFFFu, s1, 2);
        if ((lane & 3) == 0) {
            atomicAdd(&g_rsum[bm * 128 + lrow0], s0);
            atomicAdd(&g_rsum[bm * 128 + lrow0 + 8], s1);
        }
    }
}

// ---------------------------------------------------------------------------
// Kernel 3: normalize in place. One block per row.
// ---------------------------------------------------------------------------
__global__ void __launch_bounds__(256)
normalize_kernel(float* __restrict__ out) {
    int row = blockIdx.x;
    float inv = 1.0f / g_rsum[row];
    float4* p = reinterpret_cast<float4*>(out + (size_t)row * NK);
    for (int i = threadIdx.x; i < NK / 4; i += blockDim.x) {
        float4 v = p[i];
        v.x *= inv; v.y *= inv; v.z *= inv; v.w *= inv;
        p[i] = v;
    }
}

// ---------------------------------------------------------------------------
extern "C" void kernel_launch(void* const* d_in, const int* in_sizes, int n_in,
                              void* d_out, int out_size) {
    const float* Q  = (const float*)d_in[0];
    const float* Kp = (const float*)d_in[1];
    float* out = (float*)d_out;

    // 1. sumsq + bf16 split + zero row sums
    prep_kernel<<<(2 * NQ) / 8, 256>>>(Q, Kp);

    // 2. tensor-core (mma.sync) GEMM + score/exp + row sums
    dim3 grid(NK / 128, NQ / 128);
    gemm_score_kernel<<<grid, 256>>>(out);

    // 3. normalize
    normalize_kernel<<<NQ, 256>>>(out);
}